// round 6
// baseline (speedup 1.0000x reference)
#include <cuda_runtime.h>
#include <math.h>

// SwitchGate: logits = x @ W^T + b ; softmax ; top-2 mask ; masked/colsum*capacity
// N=262144, DIM=1024, E=64, TOP_K=2, capacity = N, EPS=1e-6
#define N_TOK 262144
#define DIMK  1024
#define NEXP  64
#define KC    32
#define TM    128
#define NCHUNK (DIMK / KC)   // 32

// scratch (__device__ globals: no allocation allowed)
__device__ float  g_denom[NEXP];
__device__ int    g_idx[N_TOK];
__device__ float2 g_val[N_TOK];

typedef unsigned long long ull;

__device__ __forceinline__ ull fma2(ull a, ull b, ull c) {
    ull d;
    asm("fma.rn.f32x2 %0, %1, %2, %3;" : "=l"(d) : "l"(a), "l"(b), "l"(c));
    return d;
}
__device__ __forceinline__ void unpack2(ull v, float& lo, float& hi) {
    asm("mov.b64 {%0, %1}, %2;" : "=f"(lo), "=f"(hi) : "l"(v));
}

__global__ void __launch_bounds__(64) zero_denom_k() {
    g_denom[threadIdx.x] = 0.0f;
}

// Main fused kernel: GEMM (fp32, f32x2-packed FFMA) + softmax + top2 + masked row write
// Block: 256 threads, 128 tokens x 64 experts. Thread: 4 tokens x 8 experts.
__global__ void __launch_bounds__(256, 3) gate_main_k(
    const float* __restrict__ x,
    const float* __restrict__ W,
    const float* __restrict__ b,
    float* __restrict__ out)
{
    // x tile: [kk][2*token] duplicated pairs (v,v) so LDS.64 yields the packed
    // broadcast operand for fma.rn.f32x2 directly. Stride 2*TM+2 = 258 floats
    // makes the scalar-pair stores and the 4-token reads conflict-light.
    __shared__ __align__(16) float xs[KC][2 * TM + 2];
    // W tile: [kk][expert], stride 68 (16B-aligned, reduces store conflicts,
    // keeps the two LDS.128 reads single-phase).
    __shared__ __align__(16) float ws[KC][68];

    const int tid   = threadIdx.x;
    const int ex_g  = tid & 7;    // expert group: experts [4e..4e+3] and [32+4e..32+4e+3]
    const int tok_g = tid >> 3;   // 0..31 ; octet of 8 lanes shares 4 tokens
    const int t0    = blockIdx.x * TM;

    // load-phase mapping (x): row = tid>>3 (+32p), slot = tid&7 -> float4 along K
    const int lrow  = tid >> 3;
    const int lslot = tid & 7;
    // load-phase mapping (W): row e = tid>>2, slot q = tid&3 (+4p)
    const int we = tid >> 2;
    const int wq = tid & 3;

    ull accA[4][2], accB[4][2];
#pragma unroll
    for (int r = 0; r < 4; r++) {
        accA[r][0] = accA[r][1] = 0ull;
        accB[r][0] = accB[r][1] = 0ull;
    }

    const float* xbase = x + (size_t)(t0 + lrow) * DIMK + lslot * 4;
    const float* wbase = W + (size_t)we * DIMK + wq * 4;

    // prefetch chunk 0 of x into registers
    float4 xr[4];
#pragma unroll
    for (int p = 0; p < 4; p++)
        xr[p] = *(const float4*)(xbase + (size_t)p * 32 * DIMK);

    for (int c = 0; c < NCHUNK; ++c) {
        __syncthreads();
        // store x chunk (duplicated pairs); conflict-free: bank = kk + row pattern
#pragma unroll
        for (int p = 0; p < 4; p++) {
            const int trow = lrow + 32 * p;
#pragma unroll
            for (int j = 0; j < 4; j++) {
                const float v = ((const float*)&xr[p])[j];
                *(float2*)&xs[lslot * 4 + j][2 * trow] = make_float2(v, v);
            }
        }
        // W chunk: global (L2-resident) -> smem transposed
#pragma unroll
        for (int p = 0; p < 2; p++) {
            const float4 wv = *(const float4*)(wbase + c * KC + p * 16);
#pragma unroll
            for (int j = 0; j < 4; j++)
                ws[(wq + 4 * p) * 4 + j][we] = ((const float*)&wv)[j];
        }
        __syncthreads();

        // prefetch next x chunk (overlaps with compute below)
        if (c + 1 < NCHUNK) {
#pragma unroll
            for (int p = 0; p < 4; p++)
                xr[p] = *(const float4*)(xbase + (c + 1) * KC + (size_t)p * 32 * DIMK);
        }

        // compute: per kk: 4x LDS.64 (x pairs) + 2x LDS.128 (W pairs) + 16 FFMA2
#pragma unroll
        for (int kk = 0; kk < KC; kk++) {
            const ulonglong2 wA = *(const ulonglong2*)&ws[kk][4 * ex_g];
            const ulonglong2 wB = *(const ulonglong2*)&ws[kk][32 + 4 * ex_g];
#pragma unroll
            for (int r = 0; r < 4; r++) {
                const ull xx = *(const ull*)&xs[kk][2 * (tok_g * 4 + r)];
                accA[r][0] = fma2(wA.x, xx, accA[r][0]);
                accA[r][1] = fma2(wA.y, xx, accA[r][1]);
                accB[r][0] = fma2(wB.x, xx, accB[r][0]);
                accB[r][1] = fma2(wB.y, xx, accB[r][1]);
            }
        }
    }

    // ---------------- epilogue: softmax + top2 per token via octet shuffles -----
    const float4 bA = *(const float4*)(b + 4 * ex_g);
    const float4 bB = *(const float4*)(b + 32 + 4 * ex_g);
    const unsigned fullm = 0xffffffffu;
    const int eid0 = 4 * ex_g;

#pragma unroll
    for (int r = 0; r < 4; r++) {
        float lv[8];
        unpack2(accA[r][0], lv[0], lv[1]);
        unpack2(accA[r][1], lv[2], lv[3]);
        unpack2(accB[r][0], lv[4], lv[5]);
        unpack2(accB[r][1], lv[6], lv[7]);
        lv[0] += bA.x; lv[1] += bA.y; lv[2] += bA.z; lv[3] += bA.w;
        lv[4] += bB.x; lv[5] += bB.y; lv[6] += bB.z; lv[7] += bB.w;

        // global max over 64 (octet reduce)
        float m = lv[0];
#pragma unroll
        for (int j = 1; j < 8; j++) m = fmaxf(m, lv[j]);
#pragma unroll
        for (int d = 1; d < 8; d <<= 1) m = fmaxf(m, __shfl_xor_sync(fullm, m, d));

        // sum of exp
        float s = 0.0f;
#pragma unroll
        for (int j = 0; j < 8; j++) s += expf(lv[j] - m);
#pragma unroll
        for (int d = 1; d < 8; d <<= 1) s += __shfl_xor_sync(fullm, s, d);

        // local top2 on logits (ascending expert ids -> strict > keeps lowest index)
        float v1 = lv[0]; int i1 = eid0;
        float v2 = -3.4e38f; int i2 = 127;
#pragma unroll
        for (int j = 1; j < 8; j++) {
            const int e = (j < 4) ? (eid0 + j) : (32 + eid0 + (j - 4));
            const float v = lv[j];
            if (v > v1)      { v2 = v1; i2 = i1; v1 = v; i1 = e; }
            else if (v > v2) { v2 = v;  i2 = e; }
        }
        // octet merge (ties -> lowest index, matching jax.lax.top_k)
#pragma unroll
        for (int d = 1; d < 8; d <<= 1) {
            const float ov1 = __shfl_xor_sync(fullm, v1, d);
            const int   oi1 = __shfl_xor_sync(fullm, i1, d);
            const float ov2 = __shfl_xor_sync(fullm, v2, d);
            const int   oi2 = __shfl_xor_sync(fullm, i2, d);
            const bool ofirst = (ov1 > v1) || (ov1 == v1 && oi1 < i1);
            const float n1v = ofirst ? ov1 : v1;  const int n1i = ofirst ? oi1 : i1;
            const float c1v = ofirst ? v1  : ov1; const int c1i = ofirst ? i1  : oi1;
            const float c2v = ofirst ? ov2 : v2;  const int c2i = ofirst ? oi2 : i2;
            const bool sec = (c1v > c2v) || (c1v == c2v && c1i < c2i);
            v1 = n1v; i1 = n1i;
            v2 = sec ? c1v : c2v; i2 = sec ? c1i : c2i;
        }

        const float inv = 1.0f / s;
        const float gg1 = expf(v1 - m) * inv;
        const float gg2 = expf(v2 - m) * inv;
        const int t = t0 + tok_g * 4 + r;

        float4 oA, oB;
        oA.x = (i1 == eid0 + 0) ? gg1 : (i2 == eid0 + 0) ? gg2 : 0.0f;
        oA.y = (i1 == eid0 + 1) ? gg1 : (i2 == eid0 + 1) ? gg2 : 0.0f;
        oA.z = (i1 == eid0 + 2) ? gg1 : (i2 == eid0 + 2) ? gg2 : 0.0f;
        oA.w = (i1 == eid0 + 3) ? gg1 : (i2 == eid0 + 3) ? gg2 : 0.0f;
        oB.x = (i1 == 32 + eid0 + 0) ? gg1 : (i2 == 32 + eid0 + 0) ? gg2 : 0.0f;
        oB.y = (i1 == 32 + eid0 + 1) ? gg1 : (i2 == 32 + eid0 + 1) ? gg2 : 0.0f;
        oB.z = (i1 == 32 + eid0 + 2) ? gg1 : (i2 == 32 + eid0 + 2) ? gg2 : 0.0f;
        oB.w = (i1 == 32 + eid0 + 3) ? gg1 : (i2 == 32 + eid0 + 3) ? gg2 : 0.0f;
        *(float4*)(out + (size_t)t * NEXP + 4 * ex_g)      = oA;
        *(float4*)(out + (size_t)t * NEXP + 32 + 4 * ex_g) = oB;

        if (ex_g == 0) {
            atomicAdd(&g_denom[i1], gg1);   // no return value -> REDG
            atomicAdd(&g_denom[i2], gg2);
            g_idx[t] = i1 | (i2 << 8);
            g_val[t] = make_float2(gg1, gg2);
        }
    }
}

// Rescale only the 2 nonzeros per token: out = masked * capacity / (denom + eps)
__global__ void __launch_bounds__(256) scale_out_k(float* __restrict__ out) {
    __shared__ float sc[NEXP];
    const int tid = threadIdx.x;
    if (tid < NEXP) sc[tid] = 262144.0f / (g_denom[tid] + 1e-6f);
    __syncthreads();
    const int t = blockIdx.x * 256 + tid;
    const int packed = g_idx[t];
    const float2 g = g_val[t];
    const int i1 = packed & 255;
    const int i2 = packed >> 8;
    out[(size_t)t * NEXP + i1] = g.x * sc[i1];
    out[(size_t)t * NEXP + i2] = g.y * sc[i2];
}

extern "C" void kernel_launch(void* const* d_in, const int* in_sizes, int n_in,
                              void* d_out, int out_size) {
    const float* x = (const float*)d_in[0];
    const float* W = (const float*)d_in[1];
    const float* b = (const float*)d_in[2];
    float* out = (float*)d_out;

    zero_denom_k<<<1, 64>>>();
    gate_main_k<<<N_TOK / TM, 256>>>(x, W, b, out);
    scale_out_k<<<N_TOK / 256, 256>>>(out);
}

// round 10
// speedup vs baseline: 1.7283x; 1.7283x over previous
#include <cuda_runtime.h>
#include <cuda_bf16.h>
#include <math.h>
#include <stdint.h>

// SwitchGate: logits = x @ W^T + b ; softmax ; top-2 mask ; masked/colsum*capacity
// N=262144, DIM=1024, E=64, TOP_K=2, capacity=N, EPS=1e-6
// Engine: portable mma.sync bf16 (3-term exact-split) + margin-based exact fixup.
#define N_TOK 262144
#define DIMK  1024
#define NEXP  64
#define KCH   64
#define NCH   16
#define TM    128
#define THETA 2e-4f

// ---- device scratch (no allocation allowed) ----
__device__ float  g_denom[NEXP];
__device__ int    g_idx[N_TOK];
__device__ float2 g_val[N_TOK];
__device__ int    g_nflag;
__device__ int    g_flag[N_TOK];
// pre-split, pre-swizzled bf16 W: [split hi/mid][chunk][64 rows x 128B]
__device__ __align__(16) unsigned char g_wpre[2][NCH][NEXP * 128];

__device__ __forceinline__ uint32_t smem_u32(const void* p) {
    uint32_t a;
    asm("{ .reg .u64 t; cvta.to.shared.u64 t, %1; cvt.u32.u64 %0, t; }" : "=r"(a) : "l"(p));
    return a;
}
__device__ __forceinline__ uint32_t pack_bf16x2(float even, float odd) {
    uint32_t r;  // d = {hi: odd, lo: even}
    asm("cvt.rn.bf16x2.f32 %0, %1, %2;" : "=r"(r) : "f"(odd), "f"(even));
    return r;
}

#define LDSM4(r, a) \
    asm volatile("ldmatrix.sync.aligned.m8n8.x4.shared.b16 {%0,%1,%2,%3}, [%4];" \
        : "=r"((r)[0]), "=r"((r)[1]), "=r"((r)[2]), "=r"((r)[3]) : "r"(a))

#define MMA16816(cc, a, b0, b1) \
    asm volatile("mma.sync.aligned.m16n8k16.row.col.f32.bf16.bf16.f32 " \
        "{%0,%1,%2,%3}, {%4,%5,%6,%7}, {%8,%9}, {%0,%1,%2,%3};" \
        : "+f"((cc)[0]), "+f"((cc)[1]), "+f"((cc)[2]), "+f"((cc)[3]) \
        : "r"((a)[0]), "r"((a)[1]), "r"((a)[2]), "r"((a)[3]), "r"(b0), "r"(b1))

__global__ void __launch_bounds__(64) zero_k() {
    g_denom[threadIdx.x] = 0.0f;
    if (threadIdx.x == 0) g_nflag = 0;
}

// Exact 2-way bf16 split of W, pre-swizzled (granule XOR row%8) per chunk tile.
__global__ void __launch_bounds__(256) prep_w_k(const float* __restrict__ W) {
    const int c = blockIdx.x;
    for (int i = threadIdx.x; i < NEXP * KCH; i += 256) {
        const int e = i >> 6, kl = i & 63;
        const float v = W[(size_t)e * DIMK + c * KCH + kl];
        const __nv_bfloat16 h = __float2bfloat16(v);
        const __nv_bfloat16 m = __float2bfloat16(v - __bfloat162float(h));
        const unsigned byte = e * 128 + kl * 2;
        const unsigned sw = byte ^ ((byte >> 3) & 0x70);
        *(__nv_bfloat16*)&g_wpre[0][c][sw] = h;
        *(__nv_bfloat16*)&g_wpre[1][c][sw] = m;
    }
}

// smem tile offsets (single 48KB static block)
#define XHI  0
#define XMID 16384
#define WHI  32768
#define WMID 40960

__global__ void __launch_bounds__(256, 2) gate_main_k(
    const float* __restrict__ x,
    const float* __restrict__ b,
    float* __restrict__ out)
{
    __shared__ __align__(16) unsigned char smem[49152];
    const uint32_t sbase = smem_u32(smem);

    const int tid  = threadIdx.x;
    const int wid  = tid >> 5;
    const int lane = tid & 31;
    const int t0   = blockIdx.x * TM;
    const int m0   = wid * 16;           // warp's 16 token rows

    // A-frag lane addressing (m16k16, ldmatrix.x4): tile = lane>>3
    const int atile = lane >> 3;
    const int arow  = m0 + (lane & 7) + ((atile & 1) << 3);
    const int ahalf = atile >> 1;                  // 0/1 -> +16B (k8..15)
    const unsigned axor = (unsigned)(arow & 7) << 4;
    // B-frag lane addressing: jj offset = lane>>4, half = (lane>>3)&1
    const int bj_off = lane >> 4;
    const int bhalf  = (lane >> 3) & 1;
    const unsigned bxor = (unsigned)(lane & 7) << 4;

    float cacc[8][4];
#pragma unroll
    for (int j = 0; j < 8; j++)
#pragma unroll
        for (int i = 0; i < 4; i++) cacc[j][i] = 0.0f;

    const float* xg = x + (size_t)t0 * DIMK;

    for (int c = 0; c < NCH; ++c) {
        __syncthreads();
        // ---- x chunk: load fp32 coalesced, split hi/mid bf16, swizzled STS ----
#pragma unroll
        for (int i = 0; i < 8; i++) {
            const int f   = tid + 256 * i;
            const int row = f >> 4, kq = f & 15;
            const float4 v = *(const float4*)(xg + (size_t)row * DIMK + c * KCH + kq * 4);
            const uint32_t h0 = pack_bf16x2(v.x, v.y);
            const uint32_t h1 = pack_bf16x2(v.z, v.w);
            const float r0 = v.x - __uint_as_float(h0 << 16);
            const float r1 = v.y - __uint_as_float(h0 & 0xFFFF0000u);
            const float r2 = v.z - __uint_as_float(h1 << 16);
            const float r3 = v.w - __uint_as_float(h1 & 0xFFFF0000u);
            const uint32_t md0 = pack_bf16x2(r0, r1);
            const uint32_t md1 = pack_bf16x2(r2, r3);
            const unsigned byte = row * 128 + kq * 8;
            const unsigned sw = byte ^ ((byte >> 3) & 0x70);
            *(uint2*)(smem + XHI + sw)  = make_uint2(h0, h1);
            *(uint2*)(smem + XMID + sw) = make_uint2(md0, md1);
        }
        // ---- W chunk: verbatim copy of pre-swizzled tiles (L2-resident) ----
#pragma unroll
        for (int i = 0; i < 4; i++) {
            const int idx = tid + 256 * i;
            const int sp = idx >> 9, off = idx & 511;
            ((int4*)(smem + WHI + sp * 8192))[off] = ((const int4*)g_wpre[sp][c])[off];
        }
        __syncthreads();

        // ---- MMA: 4 k-steps x (2 A-LDSM + 8 B-LDSM + 24 HMMA) ----
#pragma unroll
        for (int ks = 0; ks < 4; ks++) {
            uint32_t ah[4], am[4];
            const unsigned ab = (unsigned)(arow * 128 + ks * 32 + ahalf * 16) ^ axor;
            LDSM4(ah, sbase + XHI + ab);
            LDSM4(am, sbase + XMID + ab);
            uint32_t bh[16], bm[16];
#pragma unroll
            for (int jj = 0; jj < 4; jj++) {
                const unsigned brow = (unsigned)((2 * jj + bj_off) * 8 + (lane & 7));
                const unsigned bb = (brow * 128 + ks * 32 + bhalf * 16) ^ bxor;
                LDSM4(&bh[4 * jj], sbase + WHI + bb);
                LDSM4(&bm[4 * jj], sbase + WMID + bb);
            }
#pragma unroll
            for (int j = 0; j < 8; j++) {
                const int p = (j >> 1) * 4 + (j & 1) * 2;
                MMA16816(cacc[j], ah, bh[p], bh[p + 1]);   // hi*hi
                MMA16816(cacc[j], ah, bm[p], bm[p + 1]);   // hi*mid
                MMA16816(cacc[j], am, bh[p], bh[p + 1]);   // mid*hi
            }
        }
    }

    // ---- epilogue: quad lanes {same lane>>2} hold rows m0+g and m0+g+8 ----
    const int q = lane & 3;
    const unsigned fullm = 0xffffffffu;
    float bq[16];
#pragma unroll
    for (int j = 0; j < 8; j++) {
        bq[2 * j]     = __ldg(b + 8 * j + 2 * q);
        bq[2 * j + 1] = __ldg(b + 8 * j + 2 * q + 1);
    }

#pragma unroll
    for (int rr = 0; rr < 2; rr++) {
        const int row = m0 + (lane >> 2) + rr * 8;
        float lv[16];
#pragma unroll
        for (int j = 0; j < 8; j++) {
            lv[2 * j]     = cacc[j][2 * rr]     + bq[2 * j];
            lv[2 * j + 1] = cacc[j][2 * rr + 1] + bq[2 * j + 1];
        }
        // local top2 (expert ids ascend with index -> strict > keeps lowest id)
        float v1 = lv[0]; int i1 = 2 * q;
        float v2 = -3.4e38f; int i2 = 127;
#pragma unroll
        for (int tq = 1; tq < 16; tq++) {
            const int e = 8 * (tq >> 1) + 2 * q + (tq & 1);
            const float v = lv[tq];
            if (v > v1)      { v2 = v1; i2 = i1; v1 = v; i1 = e; }
            else if (v > v2) { v2 = v;  i2 = e; }
        }
        // quad merge (ties -> lowest index)
#pragma unroll
        for (int d = 1; d < 4; d <<= 1) {
            const float ov1 = __shfl_xor_sync(fullm, v1, d);
            const int   oi1 = __shfl_xor_sync(fullm, i1, d);
            const float ov2 = __shfl_xor_sync(fullm, v2, d);
            const int   oi2 = __shfl_xor_sync(fullm, i2, d);
            const bool of = (ov1 > v1) || (ov1 == v1 && oi1 < i1);
            const float n1v = of ? ov1 : v1;  const int n1i = of ? oi1 : i1;
            const float c1v = of ? v1  : ov1; const int c1i = of ? i1  : oi1;
            const float c2v = of ? ov2 : v2;  const int c2i = of ? oi2 : i2;
            const bool sec = (c1v > c2v) || (c1v == c2v && c1i < c2i);
            v1 = n1v; i1 = n1i;
            v2 = sec ? c1v : c2v; i2 = sec ? c1i : c2i;
        }
        // sum of exp (v1 is the global max)
        float s = 0.0f;
#pragma unroll
        for (int tq = 0; tq < 16; tq++) s += __expf(lv[tq] - v1);
#pragma unroll
        for (int d = 1; d < 4; d <<= 1) s += __shfl_xor_sync(fullm, s, d);
        // third-best (margin)
        float v3 = -3.4e38f;
#pragma unroll
        for (int tq = 0; tq < 16; tq++) {
            const int e = 8 * (tq >> 1) + 2 * q + (tq & 1);
            if (e != i1 && e != i2) v3 = fmaxf(v3, lv[tq]);
        }
#pragma unroll
        for (int d = 1; d < 4; d <<= 1) v3 = fmaxf(v3, __shfl_xor_sync(fullm, v3, d));

        const float inv = 1.0f / s;
        const float gg1 = inv;                    // exp(v1-v1)=1
        const float gg2 = __expf(v2 - v1) * inv;

        // masked row write: 8 float2 per lane; quad covers 32B segments
        float* orow = out + (size_t)(t0 + row) * NEXP;
#pragma unroll
        for (int j = 0; j < 8; j++) {
            const int e0 = 8 * j + 2 * q;
            float2 w;
            w.x = (i1 == e0)     ? gg1 : (i2 == e0)     ? gg2 : 0.0f;
            w.y = (i1 == e0 + 1) ? gg1 : (i2 == e0 + 1) ? gg2 : 0.0f;
            *(float2*)(orow + e0) = w;
        }
        if (q == 0) {
            const int t = t0 + row;
            atomicAdd(&g_denom[i1], gg1);
            atomicAdd(&g_denom[i2], gg2);
            g_idx[t] = i1 | (i2 << 8);
            g_val[t] = make_float2(gg1, gg2);
            if (v2 - v3 < THETA) {
                const int fi = atomicAdd(&g_nflag, 1);
                g_flag[fi] = t;
            }
        }
    }
}

// Exact fp32 (sequential-k order) recompute for margin-flagged tokens.
__global__ void __launch_bounds__(64) fixup_k(
    const float* __restrict__ x, const float* __restrict__ W,
    const float* __restrict__ b, float* __restrict__ out)
{
    __shared__ float lg[NEXP];
    const int nf = g_nflag;
    const int e = threadIdx.x;
    for (int i = blockIdx.x; i < nf; i += gridDim.x) {
        const int t = g_flag[i];
        const float* xp = x + (size_t)t * DIMK;
        const float* wp = W + (size_t)e * DIMK;
        float acc = 0.f;
        for (int k = 0; k < DIMK; k++) acc = fmaf(xp[k], wp[k], acc);
        lg[e] = acc + b[e];
        __syncthreads();
        if (e == 0) {
            float v1 = lg[0], v2 = -3.4e38f;
            int n1 = 0, n2 = -1;
            for (int j = 1; j < NEXP; j++) {
                const float v = lg[j];
                if (v > v1)      { v2 = v1; n2 = n1; v1 = v; n1 = j; }
                else if (v > v2) { v2 = v; n2 = j; }
            }
            const int old = g_idx[t];
            const int o1 = old & 255, o2 = old >> 8;
            const bool same = (o1 == n1 && o2 == n2) || (o1 == n2 && o2 == n1);
            if (!same) {
                float s = 0.f;
                for (int j = 0; j < NEXP; j++) s += expf(lg[j] - v1);
                const float ng1 = 1.0f / s;
                const float ng2 = expf(v2 - v1) / s;
                const float2 ov = g_val[t];
                out[(size_t)t * NEXP + o1] = 0.f;
                out[(size_t)t * NEXP + o2] = 0.f;
                out[(size_t)t * NEXP + n1] = ng1;
                out[(size_t)t * NEXP + n2] = ng2;
                atomicAdd(&g_denom[o1], -ov.x);
                atomicAdd(&g_denom[o2], -ov.y);
                atomicAdd(&g_denom[n1], ng1);
                atomicAdd(&g_denom[n2], ng2);
                g_idx[t] = n1 | (n2 << 8);
                g_val[t] = make_float2(ng1, ng2);
            }
        }
        __syncthreads();
    }
}

// Rescale only the 2 nonzeros per token: out = masked * capacity / (denom + eps)
__global__ void __launch_bounds__(256) scale_out_k(float* __restrict__ out) {
    __shared__ float sc[NEXP];
    const int tid = threadIdx.x;
    if (tid < NEXP) sc[tid] = 262144.0f / (g_denom[tid] + 1e-6f);
    __syncthreads();
    const int t = blockIdx.x * 256 + tid;
    const int packed = g_idx[t];
    const float2 g = g_val[t];
    const int i1 = packed & 255;
    const int i2 = packed >> 8;
    out[(size_t)t * NEXP + i1] = g.x * sc[i1];
    out[(size_t)t * NEXP + i2] = g.y * sc[i2];
}

extern "C" void kernel_launch(void* const* d_in, const int* in_sizes, int n_in,
                              void* d_out, int out_size) {
    const float* x = (const float*)d_in[0];
    const float* W = (const float*)d_in[1];
    const float* b = (const float*)d_in[2];
    float* out = (float*)d_out;

    zero_k<<<1, 64>>>();
    prep_w_k<<<NCH, 256>>>(W);
    gate_main_k<<<N_TOK / TM, 256>>>(x, b, out);
    fixup_k<<<128, 64>>>(x, W, b, out);
    scale_out_k<<<N_TOK / 256, 256>>>(out);
}

// round 11
// speedup vs baseline: 1.8899x; 1.0935x over previous
#include <cuda_runtime.h>
#include <cuda_bf16.h>
#include <math.h>
#include <stdint.h>

// SwitchGate: logits = x @ W^T + b ; softmax ; top-2 mask ; masked/colsum*capacity
// N=262144, DIM=1024, E=64, TOP_K=2, capacity=N, EPS=1e-6
// Engine: portable mma.sync bf16 (3-term exact-split), cp.async pipelined,
//         margin-based exact fp32 fixup (sequential-k order preserved).
#define N_TOK 262144
#define DIMK  1024
#define NEXP  64
#define KCH   64
#define NCH   16
#define TM    128
#define THETA 2e-4f

// ---- device scratch (no allocation allowed) ----
__device__ float  g_denom[NEXP];
__device__ int    g_idx[N_TOK];
__device__ float2 g_val[N_TOK];
__device__ int    g_nflag;
__device__ int    g_flag[N_TOK];
// pre-split, pre-swizzled bf16 W: [split hi/mid][chunk][64 rows x 128B]
__device__ __align__(16) unsigned char g_wpre[2][NCH][NEXP * 128];

__device__ __forceinline__ uint32_t smem_u32(const void* p) {
    uint32_t a;
    asm("{ .reg .u64 t; cvta.to.shared.u64 t, %1; cvt.u32.u64 %0, t; }" : "=r"(a) : "l"(p));
    return a;
}
__device__ __forceinline__ uint32_t pack_bf16x2(float even, float odd) {
    uint32_t r;  // d = {hi: odd, lo: even}
    asm("cvt.rn.bf16x2.f32 %0, %1, %2;" : "=r"(r) : "f"(odd), "f"(even));
    return r;
}

#define LDSM4(r, a) \
    asm volatile("ldmatrix.sync.aligned.m8n8.x4.shared.b16 {%0,%1,%2,%3}, [%4];" \
        : "=r"((r)[0]), "=r"((r)[1]), "=r"((r)[2]), "=r"((r)[3]) : "r"(a))

#define MMA16816(cc, a, b0, b1) \
    asm volatile("mma.sync.aligned.m16n8k16.row.col.f32.bf16.bf16.f32 " \
        "{%0,%1,%2,%3}, {%4,%5,%6,%7}, {%8,%9}, {%0,%1,%2,%3};" \
        : "+f"((cc)[0]), "+f"((cc)[1]), "+f"((cc)[2]), "+f"((cc)[3]) \
        : "r"((a)[0]), "r"((a)[1]), "r"((a)[2]), "r"((a)[3]), "r"(b0), "r"(b1))

#define CP16(dst, src) \
    asm volatile("cp.async.cg.shared.global [%0], [%1], 16;" :: "r"(dst), "l"(src))
#define CP_COMMIT() asm volatile("cp.async.commit_group;" ::: "memory")
#define CP_WAIT0()  asm volatile("cp.async.wait_group 0;" ::: "memory")

__global__ void __launch_bounds__(64) zero_k() {
    g_denom[threadIdx.x] = 0.0f;
    if (threadIdx.x == 0) g_nflag = 0;
}

// Exact 2-way bf16 split of W, pre-swizzled (granule XOR row%8) per chunk tile.
__global__ void __launch_bounds__(256) prep_w_k(const float* __restrict__ W) {
    const int c = blockIdx.x;
    for (int i = threadIdx.x; i < NEXP * KCH; i += 256) {
        const int e = i >> 6, kl = i & 63;
        const float v = W[(size_t)e * DIMK + c * KCH + kl];
        const __nv_bfloat16 h = __float2bfloat16(v);
        const __nv_bfloat16 m = __float2bfloat16(v - __bfloat162float(h));
        const unsigned byte = e * 128 + kl * 2;
        const unsigned sw = byte ^ ((byte >> 3) & 0x70);
        *(__nv_bfloat16*)&g_wpre[0][c][sw] = h;
        *(__nv_bfloat16*)&g_wpre[1][c][sw] = m;
    }
}

// dynamic smem layout (per CTA, 96KB):
//   XHI 0 (16K) | XMID 16K (16K) | WB0 32K (16K: hi@+0, mid@+8K) | WB1 48K (16K)
//   STAGE 64K (32K fp32 x chunk: [row][64 floats])
#define XHI   0
#define XMID  16384
#define WB(bsel) (32768 + (bsel) * 16384)
#define STAGE 65536
#define SMEM_DYN 98304

__global__ void __launch_bounds__(256, 2) gate_main_k(
    const float* __restrict__ x,
    const float* __restrict__ b,
    float* __restrict__ out)
{
    extern __shared__ __align__(16) unsigned char smem[];
    const uint32_t sbase = smem_u32(smem);

    const int tid  = threadIdx.x;
    const int wid  = tid >> 5;
    const int lane = tid & 31;
    const int t0   = blockIdx.x * TM;
    const int m0   = wid * 16;           // warp's 16 token rows

    // A-frag lane addressing (m16k16, ldmatrix.x4): tile = lane>>3
    const int atile = lane >> 3;
    const int arow  = m0 + (lane & 7) + ((atile & 1) << 3);
    const int ahalf = atile >> 1;                  // 0/1 -> +16B (k8..15)
    const unsigned axor = (unsigned)(arow & 7) << 4;
    // B-frag lane addressing: jj offset = lane>>4, half = (lane>>3)&1
    const int bj_off = lane >> 4;
    const int bhalf  = (lane >> 3) & 1;
    const unsigned bxor = (unsigned)(lane & 7) << 4;

    // fill-phase mapping: thread covers rows (tid>>4 + 16i), float4 col kq=tid&15
    const int frow0 = tid >> 4;
    const int fkq   = tid & 15;

    float cacc[8][4];
#pragma unroll
    for (int j = 0; j < 8; j++)
#pragma unroll
        for (int i = 0; i < 4; i++) cacc[j][i] = 0.0f;

    const float* xg = x + (size_t)t0 * DIMK;

    // ---- prologue: async-copy chunk 0 (x -> STAGE, W -> WB0) ----
#pragma unroll
    for (int i = 0; i < 8; i++) {
        const int row = frow0 + 16 * i;
        CP16(sbase + STAGE + row * 256 + fkq * 16,
             xg + (size_t)row * DIMK + fkq * 4);
    }
#pragma unroll
    for (int i = 0; i < 4; i++) {
        const int idx = tid + 256 * i;
        const int sp = idx >> 9, off = idx & 511;
        CP16(sbase + WB(0) + sp * 8192 + off * 16,
             (const unsigned char*)g_wpre[sp][0] + off * 16);
    }
    CP_COMMIT();

    for (int c = 0; c < NCH; ++c) {
        const int bsel = c & 1;
        CP_WAIT0();
        __syncthreads();
        // ---- convert STAGE fp32 -> split bf16 tiles (swizzled STS) ----
#pragma unroll
        for (int i = 0; i < 8; i++) {
            const int row = frow0 + 16 * i;
            const float4 v = *(const float4*)(smem + STAGE + row * 256 + fkq * 16);
            const uint32_t h0 = pack_bf16x2(v.x, v.y);
            const uint32_t h1 = pack_bf16x2(v.z, v.w);
            const float r0 = v.x - __uint_as_float(h0 << 16);
            const float r1 = v.y - __uint_as_float(h0 & 0xFFFF0000u);
            const float r2 = v.z - __uint_as_float(h1 << 16);
            const float r3 = v.w - __uint_as_float(h1 & 0xFFFF0000u);
            const uint32_t md0 = pack_bf16x2(r0, r1);
            const uint32_t md1 = pack_bf16x2(r2, r3);
            const unsigned byte = row * 128 + fkq * 8;
            const unsigned sw = byte ^ ((byte >> 3) & 0x70);
            *(uint2*)(smem + XHI + sw)  = make_uint2(h0, h1);
            *(uint2*)(smem + XMID + sw) = make_uint2(md0, md1);
        }
        __syncthreads();   // stage fully consumed; tiles ready

        // ---- issue async copies for chunk c+1 (hidden under MMA below) ----
        if (c + 1 < NCH) {
#pragma unroll
            for (int i = 0; i < 8; i++) {
                const int row = frow0 + 16 * i;
                CP16(sbase + STAGE + row * 256 + fkq * 16,
                     xg + (size_t)row * DIMK + (c + 1) * KCH + fkq * 4);
            }
#pragma unroll
            for (int i = 0; i < 4; i++) {
                const int idx = tid + 256 * i;
                const int sp = idx >> 9, off = idx & 511;
                CP16(sbase + WB(bsel ^ 1) + sp * 8192 + off * 16,
                     (const unsigned char*)g_wpre[sp][c + 1] + off * 16);
            }
            CP_COMMIT();
        }

        // ---- MMA: 4 k-steps x (2 A-LDSM + 8 B-LDSM + 24 HMMA) ----
        const uint32_t wb = sbase + WB(bsel);
#pragma unroll
        for (int ks = 0; ks < 4; ks++) {
            uint32_t ah[4], am[4];
            const unsigned ab = (unsigned)(arow * 128 + ks * 32 + ahalf * 16) ^ axor;
            LDSM4(ah, sbase + XHI + ab);
            LDSM4(am, sbase + XMID + ab);
            uint32_t bh[16], bm[16];
#pragma unroll
            for (int jj = 0; jj < 4; jj++) {
                const unsigned brow = (unsigned)((2 * jj + bj_off) * 8 + (lane & 7));
                const unsigned bb = (brow * 128 + ks * 32 + bhalf * 16) ^ bxor;
                LDSM4(&bh[4 * jj], wb + bb);
                LDSM4(&bm[4 * jj], wb + 8192 + bb);
            }
#pragma unroll
            for (int j = 0; j < 8; j++) {
                const int p = (j >> 1) * 4 + (j & 1) * 2;
                MMA16816(cacc[j], ah, bh[p], bh[p + 1]);   // hi*hi
                MMA16816(cacc[j], ah, bm[p], bm[p + 1]);   // hi*mid
                MMA16816(cacc[j], am, bh[p], bh[p + 1]);   // mid*hi
            }
        }
    }

    // ---- epilogue: quad lanes {same lane>>2} hold rows m0+g and m0+g+8 ----
    const int q = lane & 3;
    const unsigned fullm = 0xffffffffu;
    float bq[16];
#pragma unroll
    for (int j = 0; j < 8; j++) {
        bq[2 * j]     = __ldg(b + 8 * j + 2 * q);
        bq[2 * j + 1] = __ldg(b + 8 * j + 2 * q + 1);
    }

#pragma unroll
    for (int rr = 0; rr < 2; rr++) {
        const int row = m0 + (lane >> 2) + rr * 8;
        float lv[16];
#pragma unroll
        for (int j = 0; j < 8; j++) {
            lv[2 * j]     = cacc[j][2 * rr]     + bq[2 * j];
            lv[2 * j + 1] = cacc[j][2 * rr + 1] + bq[2 * j + 1];
        }
        // local top2 (expert ids ascend with index -> strict > keeps lowest id)
        float v1 = lv[0]; int i1 = 2 * q;
        float v2 = -3.4e38f; int i2 = 127;
#pragma unroll
        for (int tq = 1; tq < 16; tq++) {
            const int e = 8 * (tq >> 1) + 2 * q + (tq & 1);
            const float v = lv[tq];
            if (v > v1)      { v2 = v1; i2 = i1; v1 = v; i1 = e; }
            else if (v > v2) { v2 = v;  i2 = e; }
        }
        // quad merge (ties -> lowest index)
#pragma unroll
        for (int d = 1; d < 4; d <<= 1) {
            const float ov1 = __shfl_xor_sync(fullm, v1, d);
            const int   oi1 = __shfl_xor_sync(fullm, i1, d);
            const float ov2 = __shfl_xor_sync(fullm, v2, d);
            const int   oi2 = __shfl_xor_sync(fullm, i2, d);
            const bool of = (ov1 > v1) || (ov1 == v1 && oi1 < i1);
            const float n1v = of ? ov1 : v1;  const int n1i = of ? oi1 : i1;
            const float c1v = of ? v1  : ov1; const int c1i = of ? i1  : oi1;
            const float c2v = of ? ov2 : v2;  const int c2i = of ? oi2 : i2;
            const bool sec = (c1v > c2v) || (c1v == c2v && c1i < c2i);
            v1 = n1v; i1 = n1i;
            v2 = sec ? c1v : c2v; i2 = sec ? c1i : c2i;
        }
        // sum of exp (v1 is the global max)
        float s = 0.0f;
#pragma unroll
        for (int tq = 0; tq < 16; tq++) s += __expf(lv[tq] - v1);
#pragma unroll
        for (int d = 1; d < 4; d <<= 1) s += __shfl_xor_sync(fullm, s, d);
        // third-best (margin)
        float v3 = -3.4e38f;
#pragma unroll
        for (int tq = 0; tq < 16; tq++) {
            const int e = 8 * (tq >> 1) + 2 * q + (tq & 1);
            if (e != i1 && e != i2) v3 = fmaxf(v3, lv[tq]);
        }
#pragma unroll
        for (int d = 1; d < 4; d <<= 1) v3 = fmaxf(v3, __shfl_xor_sync(fullm, v3, d));

        const float inv = 1.0f / s;
        const float gg1 = inv;                    // exp(v1-v1)=1
        const float gg2 = __expf(v2 - v1) * inv;

        // masked row write: 8 float2 per lane; quad covers 32B segments
        float* orow = out + (size_t)(t0 + row) * NEXP;
#pragma unroll
        for (int j = 0; j < 8; j++) {
            const int e0 = 8 * j + 2 * q;
            float2 w;
            w.x = (i1 == e0)     ? gg1 : (i2 == e0)     ? gg2 : 0.0f;
            w.y = (i1 == e0 + 1) ? gg1 : (i2 == e0 + 1) ? gg2 : 0.0f;
            *(float2*)(orow + e0) = w;
        }
        if (q == 0) {
            const int t = t0 + row;
            atomicAdd(&g_denom[i1], gg1);
            atomicAdd(&g_denom[i2], gg2);
            g_idx[t] = i1 | (i2 << 8);
            g_val[t] = make_float2(gg1, gg2);
            if (v2 - v3 < THETA) {
                const int fi = atomicAdd(&g_nflag, 1);
                g_flag[fi] = t;
            }
        }
    }
}

// Exact fp32 recompute for margin-flagged tokens.
// NOTE: the per-expert sequential-k fmaf order is load-bearing (it matches the
// reference's borderline top-2 decisions) — only parallelism/scheduling changed.
__global__ void __launch_bounds__(64) fixup_k(
    const float* __restrict__ x, const float* __restrict__ W,
    const float* __restrict__ b, float* __restrict__ out)
{
    __shared__ float lg[NEXP];
    const int nf = g_nflag;
    const int e = threadIdx.x;
    for (int i = blockIdx.x; i < nf; i += gridDim.x) {
        const int t = g_flag[i];
        const float* xp = x + (size_t)t * DIMK;
        const float* wp = W + (size_t)e * DIMK;
        float acc = 0.f;
#pragma unroll 8
        for (int k = 0; k < DIMK; k++) acc = fmaf(xp[k], wp[k], acc);
        lg[e] = acc + b[e];
        __syncthreads();
        if (e == 0) {
            float v1 = lg[0], v2 = -3.4e38f;
            int n1 = 0, n2 = -1;
            for (int j = 1; j < NEXP; j++) {
                const float v = lg[j];
                if (v > v1)      { v2 = v1; n2 = n1; v1 = v; n1 = j; }
                else if (v > v2) { v2 = v; n2 = j; }
            }
            const int old = g_idx[t];
            const int o1 = old & 255, o2 = old >> 8;
            const bool same = (o1 == n1 && o2 == n2) || (o1 == n2 && o2 == n1);
            if (!same) {
                float s = 0.f;
                for (int j = 0; j < NEXP; j++) s += expf(lg[j] - v1);
                const float ng1 = 1.0f / s;
                const float ng2 = expf(v2 - v1) / s;
                const float2 ov = g_val[t];
                out[(size_t)t * NEXP + o1] = 0.f;
                out[(size_t)t * NEXP + o2] = 0.f;
                out[(size_t)t * NEXP + n1] = ng1;
                out[(size_t)t * NEXP + n2] = ng2;
                atomicAdd(&g_denom[o1], -ov.x);
                atomicAdd(&g_denom[o2], -ov.y);
                atomicAdd(&g_denom[n1], ng1);
                atomicAdd(&g_denom[n2], ng2);
                g_idx[t] = n1 | (n2 << 8);
                g_val[t] = make_float2(ng1, ng2);
            }
        }
        __syncthreads();
    }
}

// Rescale only the 2 nonzeros per token: out = masked * capacity / (denom + eps)
__global__ void __launch_bounds__(256) scale_out_k(float* __restrict__ out) {
    __shared__ float sc[NEXP];
    const int tid = threadIdx.x;
    if (tid < NEXP) sc[tid] = 262144.0f / (g_denom[tid] + 1e-6f);
    __syncthreads();
    const int t = blockIdx.x * 256 + tid;
    const int packed = g_idx[t];
    const float2 g = g_val[t];
    const int i1 = packed & 255;
    const int i2 = packed >> 8;
    out[(size_t)t * NEXP + i1] = g.x * sc[i1];
    out[(size_t)t * NEXP + i2] = g.y * sc[i2];
}

extern "C" void kernel_launch(void* const* d_in, const int* in_sizes, int n_in,
                              void* d_out, int out_size) {
    const float* x = (const float*)d_in[0];
    const float* W = (const float*)d_in[1];
    const float* b = (const float*)d_in[2];
    float* out = (float*)d_out;

    cudaFuncSetAttribute(gate_main_k, cudaFuncAttributeMaxDynamicSharedMemorySize, SMEM_DYN);

    zero_k<<<1, 64>>>();
    prep_w_k<<<NCH, 256>>>(W);
    gate_main_k<<<N_TOK / TM, 256, SMEM_DYN>>>(x, b, out);
    fixup_k<<<2048, 64>>>(x, W, b, out);
    scale_out_k<<<N_TOK / 256, 256>>>(out);
}

// round 12
// speedup vs baseline: 1.9539x; 1.0338x over previous
#include <cuda_runtime.h>
#include <cuda_bf16.h>
#include <math.h>
#include <stdint.h>

// SwitchGate: logits = x @ W^T + b ; softmax ; top-2 mask ; masked/colsum*capacity
// N=262144, DIM=1024, E=64, TOP_K=2, capacity=N, EPS=1e-6
// Engine: portable mma.sync bf16 (3-term exact-split), register-prefetch x +
//         cp.async W double-buffer, margin-based exact fp32 fixup (coalesced wT).
#define N_TOK 262144
#define DIMK  1024
#define NEXP  64
#define KCH   64
#define NCH   16
#define TM    128
#define THETA 2e-4f

// ---- device scratch (no allocation allowed) ----
__device__ float  g_denom[NEXP];
__device__ int    g_idx[N_TOK];
__device__ float2 g_val[N_TOK];
__device__ int    g_nflag;
__device__ int    g_flag[N_TOK];
// pre-split, pre-swizzled bf16 W: [split hi/mid][chunk][64 rows x 128B]
__device__ __align__(16) unsigned char g_wpre[2][NCH][NEXP * 128];
// K-major fp32 W transpose for the coalesced fixup: wT[k][e]
__device__ __align__(16) float g_wT[DIMK * NEXP];

__device__ __forceinline__ uint32_t smem_u32(const void* p) {
    uint32_t a;
    asm("{ .reg .u64 t; cvta.to.shared.u64 t, %1; cvt.u32.u64 %0, t; }" : "=r"(a) : "l"(p));
    return a;
}
__device__ __forceinline__ uint32_t pack_bf16x2(float even, float odd) {
    uint32_t r;  // d = {hi: odd, lo: even}
    asm("cvt.rn.bf16x2.f32 %0, %1, %2;" : "=r"(r) : "f"(odd), "f"(even));
    return r;
}

#define LDSM4(r, a) \
    asm volatile("ldmatrix.sync.aligned.m8n8.x4.shared.b16 {%0,%1,%2,%3}, [%4];" \
        : "=r"((r)[0]), "=r"((r)[1]), "=r"((r)[2]), "=r"((r)[3]) : "r"(a))

#define MMA16816(cc, a, b0, b1) \
    asm volatile("mma.sync.aligned.m16n8k16.row.col.f32.bf16.bf16.f32 " \
        "{%0,%1,%2,%3}, {%4,%5,%6,%7}, {%8,%9}, {%0,%1,%2,%3};" \
        : "+f"((cc)[0]), "+f"((cc)[1]), "+f"((cc)[2]), "+f"((cc)[3]) \
        : "r"((a)[0]), "r"((a)[1]), "r"((a)[2]), "r"((a)[3]), "r"(b0), "r"(b1))

#define CP16(dst, src) \
    asm volatile("cp.async.cg.shared.global [%0], [%1], 16;" :: "r"(dst), "l"(src))
#define CP_COMMIT() asm volatile("cp.async.commit_group;" ::: "memory")
#define CP_WAIT(n)  asm volatile("cp.async.wait_group %0;" :: "n"(n) : "memory")

__global__ void __launch_bounds__(64) zero_k() {
    g_denom[threadIdx.x] = 0.0f;
    if (threadIdx.x == 0) g_nflag = 0;
}

// Exact 2-way bf16 split of W (pre-swizzled tiles) + fp32 K-major transpose.
__global__ void __launch_bounds__(256) prep_w_k(const float* __restrict__ W) {
    const int c = blockIdx.x;
    for (int i = threadIdx.x; i < NEXP * KCH; i += 256) {
        const int e = i >> 6, kl = i & 63;
        const float v = W[(size_t)e * DIMK + c * KCH + kl];
        const __nv_bfloat16 h = __float2bfloat16(v);
        const __nv_bfloat16 m = __float2bfloat16(v - __bfloat162float(h));
        const unsigned byte = e * 128 + kl * 2;
        const unsigned sw = byte ^ ((byte >> 3) & 0x70);
        *(__nv_bfloat16*)&g_wpre[0][c][sw] = h;
        *(__nv_bfloat16*)&g_wpre[1][c][sw] = m;
        g_wT[(size_t)(c * KCH + kl) * NEXP + e] = v;
    }
}

// dynamic smem layout (per CTA, 64KB):
//   XHI 0 (16K) | XMID 16K (16K) | WB0 32K (hi@+0, mid@+8K) | WB1 48K
#define XHI   0
#define XMID  16384
#define WB(bsel) (32768 + (bsel) * 16384)
#define SMEM_DYN 65536

__global__ void __launch_bounds__(256, 2) gate_main_k(
    const float* __restrict__ x,
    const float* __restrict__ b,
    float* __restrict__ out)
{
    extern __shared__ __align__(16) unsigned char smem[];
    const uint32_t sbase = smem_u32(smem);

    const int tid  = threadIdx.x;
    const int wid  = tid >> 5;
    const int lane = tid & 31;
    const int t0   = blockIdx.x * TM;
    const int m0   = wid * 16;           // warp's 16 token rows

    // A-frag lane addressing (m16k16, ldmatrix.x4): tile = lane>>3
    const int atile = lane >> 3;
    const int arow  = m0 + (lane & 7) + ((atile & 1) << 3);
    const int ahalf = atile >> 1;                  // 0/1 -> +16B (k8..15)
    const unsigned axor = (unsigned)(arow & 7) << 4;
    // B-frag lane addressing: jj offset = lane>>4, half = (lane>>3)&1
    const int bj_off = lane >> 4;
    const int bhalf  = (lane >> 3) & 1;
    const unsigned bxor = (unsigned)(lane & 7) << 4;

    // fill-phase mapping: thread covers rows (tid>>4 + 16i), float4 col kq=tid&15
    const int frow0 = tid >> 4;
    const int fkq   = tid & 15;

    float cacc[8][4];
#pragma unroll
    for (int j = 0; j < 8; j++)
#pragma unroll
        for (int i = 0; i < 4; i++) cacc[j][i] = 0.0f;

    const float* xg = x + (size_t)t0 * DIMK + (size_t)frow0 * DIMK + fkq * 4;

    // ---- prologue: x chunk 0 into registers; W chunk 0 via cp.async ----
    float4 xr[8];
#pragma unroll
    for (int i = 0; i < 8; i++)
        xr[i] = *(const float4*)(xg + (size_t)i * 16 * DIMK);
#pragma unroll
    for (int i = 0; i < 4; i++) {
        const int idx = tid + 256 * i;
        const int sp = idx >> 9, off = idx & 511;
        CP16(sbase + WB(0) + sp * 8192 + off * 16,
             (const unsigned char*)g_wpre[sp][0] + off * 16);
    }
    CP_COMMIT();

    for (int c = 0; c < NCH; ++c) {
        const int bsel = c & 1;
        __syncthreads();   // previous MMA done reading X tiles
        // ---- convert xr -> split bf16 tiles; consume-and-replace prefetch ----
        const int nxt = (c + 1) * KCH;
#pragma unroll
        for (int i = 0; i < 8; i++) {
            const int row = frow0 + 16 * i;
            const float4 v = xr[i];
            if (c + 1 < NCH)
                xr[i] = *(const float4*)(xg + nxt + (size_t)i * 16 * DIMK);
            const uint32_t h0 = pack_bf16x2(v.x, v.y);
            const uint32_t h1 = pack_bf16x2(v.z, v.w);
            const float r0 = v.x - __uint_as_float(h0 << 16);
            const float r1 = v.y - __uint_as_float(h0 & 0xFFFF0000u);
            const float r2 = v.z - __uint_as_float(h1 << 16);
            const float r3 = v.w - __uint_as_float(h1 & 0xFFFF0000u);
            const uint32_t md0 = pack_bf16x2(r0, r1);
            const uint32_t md1 = pack_bf16x2(r2, r3);
            const unsigned byte = row * 128 + fkq * 8;
            const unsigned sw = byte ^ ((byte >> 3) & 0x70);
            *(uint2*)(smem + XHI + sw)  = make_uint2(h0, h1);
            *(uint2*)(smem + XMID + sw) = make_uint2(md0, md1);
        }
        // ---- W double buffer: issue c+1, ensure c has landed ----
        if (c + 1 < NCH) {
#pragma unroll
            for (int i = 0; i < 4; i++) {
                const int idx = tid + 256 * i;
                const int sp = idx >> 9, off = idx & 511;
                CP16(sbase + WB(bsel ^ 1) + sp * 8192 + off * 16,
                     (const unsigned char*)g_wpre[sp][c + 1] + off * 16);
            }
            CP_COMMIT();
            CP_WAIT(1);   // W(c) complete; W(c+1) still in flight
        } else {
            CP_WAIT(0);
        }
        __syncthreads();   // tiles + W(c) visible block-wide

        // ---- MMA: 4 k-steps x (2 A-LDSM + 8 B-LDSM + 24 HMMA) ----
        const uint32_t wb = sbase + WB(bsel);
#pragma unroll
        for (int ks = 0; ks < 4; ks++) {
            uint32_t ah[4], am[4];
            const unsigned ab = (unsigned)(arow * 128 + ks * 32 + ahalf * 16) ^ axor;
            LDSM4(ah, sbase + XHI + ab);
            LDSM4(am, sbase + XMID + ab);
            uint32_t bh[16], bm[16];
#pragma unroll
            for (int jj = 0; jj < 4; jj++) {
                const unsigned brow = (unsigned)((2 * jj + bj_off) * 8 + (lane & 7));
                const unsigned bb = (brow * 128 + ks * 32 + bhalf * 16) ^ bxor;
                LDSM4(&bh[4 * jj], wb + bb);
                LDSM4(&bm[4 * jj], wb + 8192 + bb);
            }
#pragma unroll
            for (int j = 0; j < 8; j++) {
                const int p = (j >> 1) * 4 + (j & 1) * 2;
                MMA16816(cacc[j], ah, bh[p], bh[p + 1]);   // hi*hi
                MMA16816(cacc[j], ah, bm[p], bm[p + 1]);   // hi*mid
                MMA16816(cacc[j], am, bh[p], bh[p + 1]);   // mid*hi
            }
        }
    }

    // ---- epilogue: quad lanes {same lane>>2} hold rows m0+g and m0+g+8 ----
    const int q = lane & 3;
    const unsigned fullm = 0xffffffffu;
    float bq[16];
#pragma unroll
    for (int j = 0; j < 8; j++) {
        bq[2 * j]     = __ldg(b + 8 * j + 2 * q);
        bq[2 * j + 1] = __ldg(b + 8 * j + 2 * q + 1);
    }

#pragma unroll
    for (int rr = 0; rr < 2; rr++) {
        const int row = m0 + (lane >> 2) + rr * 8;
        float lv[16];
#pragma unroll
        for (int j = 0; j < 8; j++) {
            lv[2 * j]     = cacc[j][2 * rr]     + bq[2 * j];
            lv[2 * j + 1] = cacc[j][2 * rr + 1] + bq[2 * j + 1];
        }
        // local top2 (expert ids ascend with index -> strict > keeps lowest id)
        float v1 = lv[0]; int i1 = 2 * q;
        float v2 = -3.4e38f; int i2 = 127;
#pragma unroll
        for (int tq = 1; tq < 16; tq++) {
            const int e = 8 * (tq >> 1) + 2 * q + (tq & 1);
            const float v = lv[tq];
            if (v > v1)      { v2 = v1; i2 = i1; v1 = v; i1 = e; }
            else if (v > v2) { v2 = v;  i2 = e; }
        }
        // quad merge (ties -> lowest index)
#pragma unroll
        for (int d = 1; d < 4; d <<= 1) {
            const float ov1 = __shfl_xor_sync(fullm, v1, d);
            const int   oi1 = __shfl_xor_sync(fullm, i1, d);
            const float ov2 = __shfl_xor_sync(fullm, v2, d);
            const int   oi2 = __shfl_xor_sync(fullm, i2, d);
            const bool of = (ov1 > v1) || (ov1 == v1 && oi1 < i1);
            const float n1v = of ? ov1 : v1;  const int n1i = of ? oi1 : i1;
            const float c1v = of ? v1  : ov1; const int c1i = of ? i1  : oi1;
            const float c2v = of ? ov2 : v2;  const int c2i = of ? oi2 : i2;
            const bool sec = (c1v > c2v) || (c1v == c2v && c1i < c2i);
            v1 = n1v; i1 = n1i;
            v2 = sec ? c1v : c2v; i2 = sec ? c1i : c2i;
        }
        // sum of exp (v1 is the global max)
        float s = 0.0f;
#pragma unroll
        for (int tq = 0; tq < 16; tq++) s += __expf(lv[tq] - v1);
#pragma unroll
        for (int d = 1; d < 4; d <<= 1) s += __shfl_xor_sync(fullm, s, d);
        // third-best (margin)
        float v3 = -3.4e38f;
#pragma unroll
        for (int tq = 0; tq < 16; tq++) {
            const int e = 8 * (tq >> 1) + 2 * q + (tq & 1);
            if (e != i1 && e != i2) v3 = fmaxf(v3, lv[tq]);
        }
#pragma unroll
        for (int d = 1; d < 4; d <<= 1) v3 = fmaxf(v3, __shfl_xor_sync(fullm, v3, d));

        const float inv = 1.0f / s;
        const float gg1 = inv;                    // exp(v1-v1)=1
        const float gg2 = __expf(v2 - v1) * inv;

        // masked row write: 8 float2 per lane; quad covers 32B segments
        float* orow = out + (size_t)(t0 + row) * NEXP;
#pragma unroll
        for (int j = 0; j < 8; j++) {
            const int e0 = 8 * j + 2 * q;
            float2 w;
            w.x = (i1 == e0)     ? gg1 : (i2 == e0)     ? gg2 : 0.0f;
            w.y = (i1 == e0 + 1) ? gg1 : (i2 == e0 + 1) ? gg2 : 0.0f;
            *(float2*)(orow + e0) = w;
        }
        if (q == 0) {
            const int t = t0 + row;
            atomicAdd(&g_denom[i1], gg1);
            atomicAdd(&g_denom[i2], gg2);
            g_idx[t] = i1 | (i2 << 8);
            g_val[t] = make_float2(gg1, gg2);
            if (v2 - v3 < THETA) {
                const int fi = atomicAdd(&g_nflag, 1);
                g_flag[fi] = t;
            }
        }
    }
}

// Exact fp32 recompute for margin-flagged tokens.
// Sequential-k fmaf order preserved exactly (load-bearing); W is read via the
// K-major transpose so lane accesses are coalesced (1 line/warp instead of 32).
__global__ void __launch_bounds__(64) fixup_k(
    const float* __restrict__ x,
    const float* __restrict__ b, float* __restrict__ out)
{
    __shared__ float lg[NEXP];
    const int nf = g_nflag;
    const int e = threadIdx.x;
    for (int i = blockIdx.x; i < nf; i += gridDim.x) {
        const int t = g_flag[i];
        const float* xp = x + (size_t)t * DIMK;
        const float* wp = g_wT + e;
        float acc = 0.f;
#pragma unroll 8
        for (int k = 0; k < DIMK; k++) acc = fmaf(xp[k], wp[(size_t)k * NEXP], acc);
        lg[e] = acc + b[e];
        __syncthreads();
        if (e == 0) {
            float v1 = lg[0], v2 = -3.4e38f;
            int n1 = 0, n2 = -1;
            for (int j = 1; j < NEXP; j++) {
                const float v = lg[j];
                if (v > v1)      { v2 = v1; n2 = n1; v1 = v; n1 = j; }
                else if (v > v2) { v2 = v; n2 = j; }
            }
            const int old = g_idx[t];
            const int o1 = old & 255, o2 = old >> 8;
            const bool same = (o1 == n1 && o2 == n2) || (o1 == n2 && o2 == n1);
            if (!same) {
                float s = 0.f;
                for (int j = 0; j < NEXP; j++) s += expf(lg[j] - v1);
                const float ng1 = 1.0f / s;
                const float ng2 = expf(v2 - v1) / s;
                const float2 ov = g_val[t];
                out[(size_t)t * NEXP + o1] = 0.f;
                out[(size_t)t * NEXP + o2] = 0.f;
                out[(size_t)t * NEXP + n1] = ng1;
                out[(size_t)t * NEXP + n2] = ng2;
                atomicAdd(&g_denom[o1], -ov.x);
                atomicAdd(&g_denom[o2], -ov.y);
                atomicAdd(&g_denom[n1], ng1);
                atomicAdd(&g_denom[n2], ng2);
                g_idx[t] = n1 | (n2 << 8);
                g_val[t] = make_float2(ng1, ng2);
            }
        }
        __syncthreads();
    }
}

// Rescale only the 2 nonzeros per token: out = masked * capacity / (denom + eps)
__global__ void __launch_bounds__(256) scale_out_k(float* __restrict__ out) {
    __shared__ float sc[NEXP];
    const int tid = threadIdx.x;
    if (tid < NEXP) sc[tid] = 262144.0f / (g_denom[tid] + 1e-6f);
    __syncthreads();
    const int t = blockIdx.x * 256 + tid;
    const int packed = g_idx[t];
    const float2 g = g_val[t];
    const int i1 = packed & 255;
    const int i2 = packed >> 8;
    out[(size_t)t * NEXP + i1] = g.x * sc[i1];
    out[(size_t)t * NEXP + i2] = g.y * sc[i2];
}

extern "C" void kernel_launch(void* const* d_in, const int* in_sizes, int n_in,
                              void* d_out, int out_size) {
    const float* x = (const float*)d_in[0];
    const float* W = (const float*)d_in[1];
    const float* b = (const float*)d_in[2];
    float* out = (float*)d_out;

    cudaFuncSetAttribute(gate_main_k, cudaFuncAttributeMaxDynamicSharedMemorySize, SMEM_DYN);

    zero_k<<<1, 64>>>();
    prep_w_k<<<NCH, 256>>>(W);
    gate_main_k<<<N_TOK / TM, 256, SMEM_DYN>>>(x, b, out);
    fixup_k<<<4096, 64>>>(x, b, out);
    scale_out_k<<<N_TOK / 256, 256>>>(out);
}

// round 13
// speedup vs baseline: 2.0637x; 1.0562x over previous
#include <cuda_runtime.h>
#include <cuda_bf16.h>
#include <math.h>
#include <stdint.h>

// SwitchGate: logits = x @ W^T + b ; softmax ; top-2 mask ; masked/colsum*capacity
// N=262144, DIM=1024, E=64, TOP_K=2, capacity=N, EPS=1e-6
// Engine: portable mma.sync bf16 (3-term exact-split), m32 warps (halved B-LDSM),
//         cp.async x-stage + W double-buffer, margin-based exact fp32 fixup.
#define N_TOK 262144
#define DIMK  1024
#define NEXP  64
#define KCH   64
#define NCH   16
#define TM    128
#define THETA 2e-4f

// ---- device scratch (no allocation allowed) ----
__device__ float  g_denom[NEXP];
__device__ int    g_idx[N_TOK];
__device__ float2 g_val[N_TOK];
__device__ int    g_nflag;
__device__ int    g_flag[N_TOK];
// pre-split, pre-swizzled bf16 W: [split hi/mid][chunk][64 rows x 128B]
__device__ __align__(16) unsigned char g_wpre[2][NCH][NEXP * 128];
// K-major fp32 W transpose for the coalesced fixup: wT[k][e]
__device__ __align__(16) float g_wT[DIMK * NEXP];

__device__ __forceinline__ uint32_t smem_u32(const void* p) {
    uint32_t a;
    asm("{ .reg .u64 t; cvta.to.shared.u64 t, %1; cvt.u32.u64 %0, t; }" : "=r"(a) : "l"(p));
    return a;
}
__device__ __forceinline__ uint32_t pack_bf16x2(float even, float odd) {
    uint32_t r;  // d = {hi: odd, lo: even}
    asm("cvt.rn.bf16x2.f32 %0, %1, %2;" : "=r"(r) : "f"(odd), "f"(even));
    return r;
}

#define LDSM4(r, a) \
    asm volatile("ldmatrix.sync.aligned.m8n8.x4.shared.b16 {%0,%1,%2,%3}, [%4];" \
        : "=r"((r)[0]), "=r"((r)[1]), "=r"((r)[2]), "=r"((r)[3]) : "r"(a))

#define MMA16816(cc, a, b0, b1) \
    asm volatile("mma.sync.aligned.m16n8k16.row.col.f32.bf16.bf16.f32 " \
        "{%0,%1,%2,%3}, {%4,%5,%6,%7}, {%8,%9}, {%0,%1,%2,%3};" \
        : "+f"((cc)[0]), "+f"((cc)[1]), "+f"((cc)[2]), "+f"((cc)[3]) \
        : "r"((a)[0]), "r"((a)[1]), "r"((a)[2]), "r"((a)[3]), "r"(b0), "r"(b1))

#define CP16(dst, src) \
    asm volatile("cp.async.cg.shared.global [%0], [%1], 16;" :: "r"(dst), "l"(src))
#define CP_COMMIT() asm volatile("cp.async.commit_group;" ::: "memory")
#define CP_WAIT(n)  asm volatile("cp.async.wait_group %0;" :: "n"(n) : "memory")

__global__ void __launch_bounds__(64) zero_k() {
    g_denom[threadIdx.x] = 0.0f;
    if (threadIdx.x == 0) g_nflag = 0;
}

// Exact 2-way bf16 split of W (pre-swizzled tiles) + fp32 K-major transpose.
__global__ void __launch_bounds__(256) prep_w_k(const float* __restrict__ W) {
    const int c = blockIdx.x;
    for (int i = threadIdx.x; i < NEXP * KCH; i += 256) {
        const int e = i >> 6, kl = i & 63;
        const float v = W[(size_t)e * DIMK + c * KCH + kl];
        const __nv_bfloat16 h = __float2bfloat16(v);
        const __nv_bfloat16 m = __float2bfloat16(v - __bfloat162float(h));
        const unsigned byte = e * 128 + kl * 2;
        const unsigned sw = byte ^ ((byte >> 3) & 0x70);
        *(__nv_bfloat16*)&g_wpre[0][c][sw] = h;
        *(__nv_bfloat16*)&g_wpre[1][c][sw] = m;
        g_wT[(size_t)(c * KCH + kl) * NEXP + e] = v;
    }
}

// dynamic smem (per CTA, 96KB):
//   XHI 0 (16K) | XMID 16K | WB0 32K (hi@+0, mid@+8K) | WB1 48K | STAGE 64K (32K)
#define XHI   0
#define XMID  16384
#define WB(bsel) (32768 + (bsel) * 16384)
#define STAGE 65536
#define SMEM_DYN 98304

// 128 threads, 4 warps; each warp computes m32 (rows 32*wid .. 32*wid+31).
__global__ void __launch_bounds__(128, 2) gate_main_k(
    const float* __restrict__ x,
    const float* __restrict__ b,
    float* __restrict__ out)
{
    extern __shared__ __align__(16) unsigned char smem[];
    const uint32_t sbase = smem_u32(smem);

    const int tid  = threadIdx.x;
    const int wid  = tid >> 5;
    const int lane = tid & 31;
    const int t0   = blockIdx.x * TM;
    const int m0   = wid * 32;           // warp's 32 token rows

    // A-frag lane addressing (m16k16, ldmatrix.x4): tile = lane>>3
    const int atile = lane >> 3;
    const int arow_b = m0 + (lane & 7) + ((atile & 1) << 3);  // + 16*mset
    const int ahalf  = atile >> 1;                 // 0/1 -> +16B (k8..15)
    const unsigned axor = (unsigned)(lane & 7) << 4;
    // B-frag lane addressing: jj offset = lane>>4, half = (lane>>3)&1
    const int bj_off = lane >> 4;
    const int bhalf  = (lane >> 3) & 1;
    const unsigned bxor = (unsigned)(lane & 7) << 4;

    // fill mapping: thread covers rows (tid>>4 + 8i), float4 col fkq
    const int frow0 = tid >> 4;   // 0..7
    const int fkq   = tid & 15;

    float cacc[2][8][4];
#pragma unroll
    for (int ms = 0; ms < 2; ms++)
#pragma unroll
        for (int j = 0; j < 8; j++)
#pragma unroll
            for (int i = 0; i < 4; i++) cacc[ms][j][i] = 0.0f;

    // ---- prologue: cp.async stage(0) + W(0) ----
#pragma unroll
    for (int i = 0; i < 16; i++) {
        const int row = frow0 + 8 * i;
        CP16(sbase + STAGE + row * 256 + fkq * 16,
             x + (size_t)(t0 + row) * DIMK + fkq * 4);
    }
#pragma unroll
    for (int i = 0; i < 8; i++) {
        const int idx = tid + 128 * i;            // 0..1023 int4
        const int sp = idx >> 9, off = idx & 511;
        CP16(sbase + WB(0) + sp * 8192 + off * 16,
             (const unsigned char*)g_wpre[sp][0] + off * 16);
    }
    CP_COMMIT();

    for (int c = 0; c < NCH; ++c) {
        const int bsel = c & 1;
        CP_WAIT(0);
        __syncthreads();   // stage(c)+W(c) landed; MMA(c-1) done with X tiles
        // ---- convert stage fp32 -> split bf16 tiles (swizzled STS) ----
#pragma unroll
        for (int i = 0; i < 16; i++) {
            const int row = frow0 + 8 * i;
            const float4 v = *(const float4*)(smem + STAGE + row * 256 + fkq * 16);
            const uint32_t h0 = pack_bf16x2(v.x, v.y);
            const uint32_t h1 = pack_bf16x2(v.z, v.w);
            const float r0 = v.x - __uint_as_float(h0 << 16);
            const float r1 = v.y - __uint_as_float(h0 & 0xFFFF0000u);
            const float r2 = v.z - __uint_as_float(h1 << 16);
            const float r3 = v.w - __uint_as_float(h1 & 0xFFFF0000u);
            const uint32_t md0 = pack_bf16x2(r0, r1);
            const uint32_t md1 = pack_bf16x2(r2, r3);
            const unsigned byte = row * 128 + fkq * 8;
            const unsigned sw = byte ^ ((byte >> 3) & 0x70);
            *(uint2*)(smem + XHI + sw)  = make_uint2(h0, h1);
            *(uint2*)(smem + XMID + sw) = make_uint2(md0, md1);
        }
        __syncthreads();   // stage consumed; X tiles ready

        // ---- issue stage(c+1) + W(c+1): overlaps the MMA below ----
        if (c + 1 < NCH) {
            const int nxt = (c + 1) * KCH;
#pragma unroll
            for (int i = 0; i < 16; i++) {
                const int row = frow0 + 8 * i;
                CP16(sbase + STAGE + row * 256 + fkq * 16,
                     x + (size_t)(t0 + row) * DIMK + nxt + fkq * 4);
            }
#pragma unroll
            for (int i = 0; i < 8; i++) {
                const int idx = tid + 128 * i;
                const int sp = idx >> 9, off = idx & 511;
                CP16(sbase + WB(bsel ^ 1) + sp * 8192 + off * 16,
                     (const unsigned char*)g_wpre[sp][c + 1] + off * 16);
            }
            CP_COMMIT();
        }

        // ---- MMA: 4 ks x (8 B-LDSM + 2x(2 A-LDSM + 24 HMMA)) ----
        const uint32_t wb = sbase + WB(bsel);
#pragma unroll
        for (int ks = 0; ks < 4; ks++) {
            uint32_t bh[16], bm[16];
#pragma unroll
            for (int jj = 0; jj < 4; jj++) {
                const unsigned brow = (unsigned)((2 * jj + bj_off) * 8 + (lane & 7));
                const unsigned bb = (brow * 128 + ks * 32 + bhalf * 16) ^ bxor;
                LDSM4(&bh[4 * jj], wb + bb);
                LDSM4(&bm[4 * jj], wb + 8192 + bb);
            }
#pragma unroll
            for (int ms = 0; ms < 2; ms++) {
                uint32_t ah[4], am[4];
                const unsigned ab =
                    (unsigned)((arow_b + 16 * ms) * 128 + ks * 32 + ahalf * 16) ^ axor;
                LDSM4(ah, sbase + XHI + ab);
                LDSM4(am, sbase + XMID + ab);
#pragma unroll
                for (int j = 0; j < 8; j++) {
                    const int p = (j >> 1) * 4 + (j & 1) * 2;
                    MMA16816(cacc[ms][j], ah, bh[p], bh[p + 1]);   // hi*hi
                    MMA16816(cacc[ms][j], ah, bm[p], bm[p + 1]);   // hi*mid
                    MMA16816(cacc[ms][j], am, bh[p], bh[p + 1]);   // mid*hi
                }
            }
        }
    }

    // ---- epilogue: quad lanes hold rows m0+16*ms+8*rr+(lane>>2) ----
    const int q = lane & 3;
    const unsigned fullm = 0xffffffffu;
    float bq[16];
#pragma unroll
    for (int j = 0; j < 8; j++) {
        bq[2 * j]     = __ldg(b + 8 * j + 2 * q);
        bq[2 * j + 1] = __ldg(b + 8 * j + 2 * q + 1);
    }

#pragma unroll
    for (int ms = 0; ms < 2; ms++)
#pragma unroll
    for (int rr = 0; rr < 2; rr++) {
        const int row = m0 + 16 * ms + (lane >> 2) + rr * 8;
        float lv[16];
#pragma unroll
        for (int j = 0; j < 8; j++) {
            lv[2 * j]     = cacc[ms][j][2 * rr]     + bq[2 * j];
            lv[2 * j + 1] = cacc[ms][j][2 * rr + 1] + bq[2 * j + 1];
        }
        // local top2 (expert ids ascend with index -> strict > keeps lowest id)
        float v1 = lv[0]; int i1 = 2 * q;
        float v2 = -3.4e38f; int i2 = 127;
#pragma unroll
        for (int tq = 1; tq < 16; tq++) {
            const int e = 8 * (tq >> 1) + 2 * q + (tq & 1);
            const float v = lv[tq];
            if (v > v1)      { v2 = v1; i2 = i1; v1 = v; i1 = e; }
            else if (v > v2) { v2 = v;  i2 = e; }
        }
        // quad merge (ties -> lowest index)
#pragma unroll
        for (int d = 1; d < 4; d <<= 1) {
            const float ov1 = __shfl_xor_sync(fullm, v1, d);
            const int   oi1 = __shfl_xor_sync(fullm, i1, d);
            const float ov2 = __shfl_xor_sync(fullm, v2, d);
            const int   oi2 = __shfl_xor_sync(fullm, i2, d);
            const bool of = (ov1 > v1) || (ov1 == v1 && oi1 < i1);
            const float n1v = of ? ov1 : v1;  const int n1i = of ? oi1 : i1;
            const float c1v = of ? v1  : ov1; const int c1i = of ? i1  : oi1;
            const float c2v = of ? ov2 : v2;  const int c2i = of ? oi2 : i2;
            const bool sec = (c1v > c2v) || (c1v == c2v && c1i < c2i);
            v1 = n1v; i1 = n1i;
            v2 = sec ? c1v : c2v; i2 = sec ? c1i : c2i;
        }
        // sum of exp (v1 is the global max)
        float s = 0.0f;
#pragma unroll
        for (int tq = 0; tq < 16; tq++) s += __expf(lv[tq] - v1);
#pragma unroll
        for (int d = 1; d < 4; d <<= 1) s += __shfl_xor_sync(fullm, s, d);
        // third-best (margin)
        float v3 = -3.4e38f;
#pragma unroll
        for (int tq = 0; tq < 16; tq++) {
            const int e = 8 * (tq >> 1) + 2 * q + (tq & 1);
            if (e != i1 && e != i2) v3 = fmaxf(v3, lv[tq]);
        }
#pragma unroll
        for (int d = 1; d < 4; d <<= 1) v3 = fmaxf(v3, __shfl_xor_sync(fullm, v3, d));

        const float inv = 1.0f / s;
        const float gg1 = inv;                    // exp(v1-v1)=1
        const float gg2 = __expf(v2 - v1) * inv;

        // masked row write: 8 float2 per lane; quad covers 32B segments
        float* orow = out + (size_t)(t0 + row) * NEXP;
#pragma unroll
        for (int j = 0; j < 8; j++) {
            const int e0 = 8 * j + 2 * q;
            float2 w;
            w.x = (i1 == e0)     ? gg1 : (i2 == e0)     ? gg2 : 0.0f;
            w.y = (i1 == e0 + 1) ? gg1 : (i2 == e0 + 1) ? gg2 : 0.0f;
            *(float2*)(orow + e0) = w;
        }
        if (q == 0) {
            const int t = t0 + row;
            atomicAdd(&g_denom[i1], gg1);
            atomicAdd(&g_denom[i2], gg2);
            g_idx[t] = i1 | (i2 << 8);
            g_val[t] = make_float2(gg1, gg2);
            if (v2 - v3 < THETA) {
                const int fi = atomicAdd(&g_nflag, 1);
                g_flag[fi] = t;
            }
        }
    }
}

// Exact fp32 recompute for margin-flagged tokens.
// The sequential-k fmaf order is load-bearing (matches the reference's
// borderline top-2). x staged in smem (coalesced), wT read coalesced with
// unroll-16 batching for deep MLP.
__global__ void __launch_bounds__(64) fixup_k(
    const float* __restrict__ x,
    const float* __restrict__ b, float* __restrict__ out)
{
    __shared__ __align__(16) float xs[DIMK];
    __shared__ float lg[NEXP];
    const int nf = g_nflag;
    const int e = threadIdx.x;
    for (int i = blockIdx.x; i < nf; i += gridDim.x) {
        const int t = g_flag[i];
        // cooperative coalesced stage of the token's x row
        const float4* xsrc = (const float4*)(x + (size_t)t * DIMK);
#pragma unroll
        for (int p = 0; p < 4; p++)
            ((float4*)xs)[e + 64 * p] = xsrc[e + 64 * p];
        __syncthreads();
        const float* wp = g_wT + e;
        float acc = 0.f;
#pragma unroll 16
        for (int k = 0; k < DIMK; k++) acc = fmaf(xs[k], wp[(size_t)k * NEXP], acc);
        lg[e] = acc + b[e];
        __syncthreads();
        if (e == 0) {
            float v1 = lg[0], v2 = -3.4e38f;
            int n1 = 0, n2 = -1;
            for (int j = 1; j < NEXP; j++) {
                const float v = lg[j];
                if (v > v1)      { v2 = v1; n2 = n1; v1 = v; n1 = j; }
                else if (v > v2) { v2 = v; n2 = j; }
            }
            const int old = g_idx[t];
            const int o1 = old & 255, o2 = old >> 8;
            const bool same = (o1 == n1 && o2 == n2) || (o1 == n2 && o2 == n1);
            if (!same) {
                float s = 0.f;
                for (int j = 0; j < NEXP; j++) s += expf(lg[j] - v1);
                const float ng1 = 1.0f / s;
                const float ng2 = expf(v2 - v1) / s;
                const float2 ov = g_val[t];
                out[(size_t)t * NEXP + o1] = 0.f;
                out[(size_t)t * NEXP + o2] = 0.f;
                out[(size_t)t * NEXP + n1] = ng1;
                out[(size_t)t * NEXP + n2] = ng2;
                atomicAdd(&g_denom[o1], -ov.x);
                atomicAdd(&g_denom[o2], -ov.y);
                atomicAdd(&g_denom[n1], ng1);
                atomicAdd(&g_denom[n2], ng2);
                g_idx[t] = n1 | (n2 << 8);
                g_val[t] = make_float2(ng1, ng2);
            }
        }
        __syncthreads();
    }
}

// Rescale only the 2 nonzeros per token: out = masked * capacity / (denom + eps)
__global__ void __launch_bounds__(256) scale_out_k(float* __restrict__ out) {
    __shared__ float sc[NEXP];
    const int tid = threadIdx.x;
    if (tid < NEXP) sc[tid] = 262144.0f / (g_denom[tid] + 1e-6f);
    __syncthreads();
    const int t = blockIdx.x * 256 + tid;
    const int packed = g_idx[t];
    const float2 g = g_val[t];
    const int i1 = packed & 255;
    const int i2 = packed >> 8;
    out[(size_t)t * NEXP + i1] = g.x * sc[i1];
    out[(size_t)t * NEXP + i2] = g.y * sc[i2];
}

extern "C" void kernel_launch(void* const* d_in, const int* in_sizes, int n_in,
                              void* d_out, int out_size) {
    const float* x = (const float*)d_in[0];
    const float* W = (const float*)d_in[1];
    const float* b = (const float*)d_in[2];
    float* out = (float*)d_out;

    cudaFuncSetAttribute(gate_main_k, cudaFuncAttributeMaxDynamicSharedMemorySize, SMEM_DYN);

    zero_k<<<1, 64>>>();
    prep_w_k<<<NCH, 256>>>(W);
    gate_main_k<<<N_TOK / TM, 128, SMEM_DYN>>>(x, b, out);
    fixup_k<<<4096, 64>>>(x, b, out);
    scale_out_k<<<N_TOK / 256, 256>>>(out);
}

// round 16
// speedup vs baseline: 2.2114x; 1.0716x over previous
#include <cuda_runtime.h>
#include <cuda_bf16.h>
#include <math.h>
#include <stdint.h>

// SwitchGate: logits = x @ W^T + b ; softmax ; top-2 mask ; masked/colsum*capacity
// N=262144, DIM=1024, E=64, TOP_K=2, capacity=N, EPS=1e-6
// Engine: portable mma.sync bf16 (3-term exact-split), m32 warps, cp.async
// pipeline; compact sideband (idx/val) -> single coalesced output pass.
#define N_TOK 262144
#define DIMK  1024
#define NEXP  64
#define KCH   64
#define NCH   16
#define TM    128
#define THETA 2e-4f

// ---- device scratch (no allocation allowed) ----
__device__ float  g_denom[NEXP];
__device__ int    g_idx[N_TOK];
__device__ float2 g_val[N_TOK];
__device__ int    g_nflag;
__device__ int    g_flag[N_TOK];
// pre-split, pre-swizzled bf16 W: [split hi/mid][chunk][64 rows x 128B]
__device__ __align__(16) unsigned char g_wpre[2][NCH][NEXP * 128];
// K-major fp32 W transpose for the coalesced fixup: wT[k][e]
__device__ __align__(16) float g_wT[DIMK * NEXP];

__device__ __forceinline__ uint32_t smem_u32(const void* p) {
    uint32_t a;
    asm("{ .reg .u64 t; cvta.to.shared.u64 t, %1; cvt.u32.u64 %0, t; }" : "=r"(a) : "l"(p));
    return a;
}
__device__ __forceinline__ uint32_t pack_bf16x2(float even, float odd) {
    uint32_t r;  // d = {hi: odd, lo: even}
    asm("cvt.rn.bf16x2.f32 %0, %1, %2;" : "=r"(r) : "f"(odd), "f"(even));
    return r;
}

#define LDSM4(r, a) \
    asm volatile("ldmatrix.sync.aligned.m8n8.x4.shared.b16 {%0,%1,%2,%3}, [%4];" \
        : "=r"((r)[0]), "=r"((r)[1]), "=r"((r)[2]), "=r"((r)[3]) : "r"(a))

#define MMA16816(cc, a, b0, b1) \
    asm volatile("mma.sync.aligned.m16n8k16.row.col.f32.bf16.bf16.f32 " \
        "{%0,%1,%2,%3}, {%4,%5,%6,%7}, {%8,%9}, {%0,%1,%2,%3};" \
        : "+f"((cc)[0]), "+f"((cc)[1]), "+f"((cc)[2]), "+f"((cc)[3]) \
        : "r"((a)[0]), "r"((a)[1]), "r"((a)[2]), "r"((a)[3]), "r"(b0), "r"(b1))

#define CP16(dst, src) \
    asm volatile("cp.async.cg.shared.global [%0], [%1], 16;" :: "r"(dst), "l"(src))
#define CP_COMMIT() asm volatile("cp.async.commit_group;" ::: "memory")
#define CP_WAIT(n)  asm volatile("cp.async.wait_group %0;" :: "n"(n) : "memory")

__global__ void __launch_bounds__(64) zero_k() {
    g_denom[threadIdx.x] = 0.0f;
    if (threadIdx.x == 0) g_nflag = 0;
}

// Exact 2-way bf16 split of W (pre-swizzled tiles) + fp32 K-major transpose.
__global__ void __launch_bounds__(256) prep_w_k(const float* __restrict__ W) {
    const int c = blockIdx.x;
    for (int i = threadIdx.x; i < NEXP * KCH; i += 256) {
        const int e = i >> 6, kl = i & 63;
        const float v = W[(size_t)e * DIMK + c * KCH + kl];
        const __nv_bfloat16 h = __float2bfloat16(v);
        const __nv_bfloat16 m = __float2bfloat16(v - __bfloat162float(h));
        const unsigned byte = e * 128 + kl * 2;
        const unsigned sw = byte ^ ((byte >> 3) & 0x70);
        *(__nv_bfloat16*)&g_wpre[0][c][sw] = h;
        *(__nv_bfloat16*)&g_wpre[1][c][sw] = m;
        g_wT[(size_t)(c * KCH + kl) * NEXP + e] = v;
    }
}

// dynamic smem (per CTA, 96KB):
//   XHI 0 (16K) | XMID 16K | WB0 32K (hi@+0, mid@+8K) | WB1 48K | STAGE 64K (32K)
#define XHI   0
#define XMID  16384
#define WB(bsel) (32768 + (bsel) * 16384)
#define STAGE 65536
#define SMEM_DYN 98304

// 128 threads, 4 warps; each warp computes m32 (rows 32*wid .. 32*wid+31).
// Writes ONLY the compact sideband (g_idx/g_val/g_denom/flags) — the output
// rows are materialized once, coalesced, in scale_out_k.
__global__ void __launch_bounds__(128, 2) gate_main_k(
    const float* __restrict__ x,
    const float* __restrict__ b)
{
    extern __shared__ __align__(16) unsigned char smem[];
    const uint32_t sbase = smem_u32(smem);

    const int tid  = threadIdx.x;
    const int wid  = tid >> 5;
    const int lane = tid & 31;
    const int t0   = blockIdx.x * TM;
    const int m0   = wid * 32;           // warp's 32 token rows

    // A-frag lane addressing (m16k16, ldmatrix.x4): tile = lane>>3
    const int atile = lane >> 3;
    const int arow_b = m0 + (lane & 7) + ((atile & 1) << 3);  // + 16*mset
    const int ahalf  = atile >> 1;                 // 0/1 -> +16B (k8..15)
    const unsigned axor = (unsigned)(lane & 7) << 4;
    // B-frag lane addressing: jj offset = lane>>4, half = (lane>>3)&1
    const int bj_off = lane >> 4;
    const int bhalf  = (lane >> 3) & 1;
    const unsigned bxor = (unsigned)(lane & 7) << 4;

    // fill mapping: thread covers rows (tid>>4 + 8i), float4 col fkq
    const int frow0 = tid >> 4;   // 0..7
    const int fkq   = tid & 15;

    float cacc[2][8][4];
#pragma unroll
    for (int ms = 0; ms < 2; ms++)
#pragma unroll
        for (int j = 0; j < 8; j++)
#pragma unroll
            for (int i = 0; i < 4; i++) cacc[ms][j][i] = 0.0f;

    // ---- prologue: cp.async stage(0) + W(0) ----
#pragma unroll
    for (int i = 0; i < 16; i++) {
        const int row = frow0 + 8 * i;
        CP16(sbase + STAGE + row * 256 + fkq * 16,
             x + (size_t)(t0 + row) * DIMK + fkq * 4);
    }
#pragma unroll
    for (int i = 0; i < 8; i++) {
        const int idx = tid + 128 * i;            // 0..1023 int4
        const int sp = idx >> 9, off = idx & 511;
        CP16(sbase + WB(0) + sp * 8192 + off * 16,
             (const unsigned char*)g_wpre[sp][0] + off * 16);
    }
    CP_COMMIT();

    for (int c = 0; c < NCH; ++c) {
        const int bsel = c & 1;
        CP_WAIT(0);
        __syncthreads();   // stage(c)+W(c) landed; MMA(c-1) done with X tiles
        // ---- convert stage fp32 -> split bf16 tiles (swizzled STS) ----
#pragma unroll
        for (int i = 0; i < 16; i++) {
            const int row = frow0 + 8 * i;
            const float4 v = *(const float4*)(smem + STAGE + row * 256 + fkq * 16);
            const uint32_t h0 = pack_bf16x2(v.x, v.y);
            const uint32_t h1 = pack_bf16x2(v.z, v.w);
            const float r0 = v.x - __uint_as_float(h0 << 16);
            const float r1 = v.y - __uint_as_float(h0 & 0xFFFF0000u);
            const float r2 = v.z - __uint_as_float(h1 << 16);
            const float r3 = v.w - __uint_as_float(h1 & 0xFFFF0000u);
            const uint32_t md0 = pack_bf16x2(r0, r1);
            const uint32_t md1 = pack_bf16x2(r2, r3);
            const unsigned byte = row * 128 + fkq * 8;
            const unsigned sw = byte ^ ((byte >> 3) & 0x70);
            *(uint2*)(smem + XHI + sw)  = make_uint2(h0, h1);
            *(uint2*)(smem + XMID + sw) = make_uint2(md0, md1);
        }
        __syncthreads();   // stage consumed; X tiles ready

        // ---- issue stage(c+1) + W(c+1): overlaps the MMA below ----
        if (c + 1 < NCH) {
            const int nxt = (c + 1) * KCH;
#pragma unroll
            for (int i = 0; i < 16; i++) {
                const int row = frow0 + 8 * i;
                CP16(sbase + STAGE + row * 256 + fkq * 16,
                     x + (size_t)(t0 + row) * DIMK + nxt + fkq * 4);
            }
#pragma unroll
            for (int i = 0; i < 8; i++) {
                const int idx = tid + 128 * i;
                const int sp = idx >> 9, off = idx & 511;
                CP16(sbase + WB(bsel ^ 1) + sp * 8192 + off * 16,
                     (const unsigned char*)g_wpre[sp][c + 1] + off * 16);
            }
            CP_COMMIT();
        }

        // ---- MMA: 4 ks x (8 B-LDSM + 2x(2 A-LDSM + 24 HMMA)) ----
        const uint32_t wb = sbase + WB(bsel);
#pragma unroll
        for (int ks = 0; ks < 4; ks++) {
            uint32_t bh[16], bm[16];
#pragma unroll
            for (int jj = 0; jj < 4; jj++) {
                const unsigned brow = (unsigned)((2 * jj + bj_off) * 8 + (lane & 7));
                const unsigned bb = (brow * 128 + ks * 32 + bhalf * 16) ^ bxor;
                LDSM4(&bh[4 * jj], wb + bb);
                LDSM4(&bm[4 * jj], wb + 8192 + bb);
            }
#pragma unroll
            for (int ms = 0; ms < 2; ms++) {
                uint32_t ah[4], am[4];
                const unsigned ab =
                    (unsigned)((arow_b + 16 * ms) * 128 + ks * 32 + ahalf * 16) ^ axor;
                LDSM4(ah, sbase + XHI + ab);
                LDSM4(am, sbase + XMID + ab);
#pragma unroll
                for (int j = 0; j < 8; j++) {
                    const int p = (j >> 1) * 4 + (j & 1) * 2;
                    MMA16816(cacc[ms][j], ah, bh[p], bh[p + 1]);   // hi*hi
                    MMA16816(cacc[ms][j], ah, bm[p], bm[p + 1]);   // hi*mid
                    MMA16816(cacc[ms][j], am, bh[p], bh[p + 1]);   // mid*hi
                }
            }
        }
    }

    // ---- epilogue: quad lanes hold rows m0+16*ms+8*rr+(lane>>2) ----
    const int q = lane & 3;
    const unsigned fullm = 0xffffffffu;
    float bq[16];
#pragma unroll
    for (int j = 0; j < 8; j++) {
        bq[2 * j]     = __ldg(b + 8 * j + 2 * q);
        bq[2 * j + 1] = __ldg(b + 8 * j + 2 * q + 1);
    }

#pragma unroll
    for (int ms = 0; ms < 2; ms++)
#pragma unroll
    for (int rr = 0; rr < 2; rr++) {
        const int row = m0 + 16 * ms + (lane >> 2) + rr * 8;
        float lv[16];
#pragma unroll
        for (int j = 0; j < 8; j++) {
            lv[2 * j]     = cacc[ms][j][2 * rr]     + bq[2 * j];
            lv[2 * j + 1] = cacc[ms][j][2 * rr + 1] + bq[2 * j + 1];
        }
        // local top2 (expert ids ascend with index -> strict > keeps lowest id)
        float v1 = lv[0]; int i1 = 2 * q;
        float v2 = -3.4e38f; int i2 = 127;
#pragma unroll
        for (int tq = 1; tq < 16; tq++) {
            const int e = 8 * (tq >> 1) + 2 * q + (tq & 1);
            const float v = lv[tq];
            if (v > v1)      { v2 = v1; i2 = i1; v1 = v; i1 = e; }
            else if (v > v2) { v2 = v;  i2 = e; }
        }
        // quad merge (ties -> lowest index)
#pragma unroll
        for (int d = 1; d < 4; d <<= 1) {
            const float ov1 = __shfl_xor_sync(fullm, v1, d);
            const int   oi1 = __shfl_xor_sync(fullm, i1, d);
            const float ov2 = __shfl_xor_sync(fullm, v2, d);
            const int   oi2 = __shfl_xor_sync(fullm, i2, d);
            const bool of = (ov1 > v1) || (ov1 == v1 && oi1 < i1);
            const float n1v = of ? ov1 : v1;  const int n1i = of ? oi1 : i1;
            const float c1v = of ? v1  : ov1; const int c1i = of ? i1  : oi1;
            const float c2v = of ? ov2 : v2;  const int c2i = of ? oi2 : i2;
            const bool sec = (c1v > c2v) || (c1v == c2v && c1i < c2i);
            v1 = n1v; i1 = n1i;
            v2 = sec ? c1v : c2v; i2 = sec ? c1i : c2i;
        }
        // sum of exp (v1 is the global max)
        float s = 0.0f;
#pragma unroll
        for (int tq = 0; tq < 16; tq++) s += __expf(lv[tq] - v1);
#pragma unroll
        for (int d = 1; d < 4; d <<= 1) s += __shfl_xor_sync(fullm, s, d);
        // third-best (margin)
        float v3 = -3.4e38f;
#pragma unroll
        for (int tq = 0; tq < 16; tq++) {
            const int e = 8 * (tq >> 1) + 2 * q + (tq & 1);
            if (e != i1 && e != i2) v3 = fmaxf(v3, lv[tq]);
        }
#pragma unroll
        for (int d = 1; d < 4; d <<= 1) v3 = fmaxf(v3, __shfl_xor_sync(fullm, v3, d));

        if (q == 0) {
            const float inv = 1.0f / s;
            const float gg1 = inv;                    // exp(v1-v1)=1
            const float gg2 = __expf(v2 - v1) * inv;
            const int t = t0 + row;
            atomicAdd(&g_denom[i1], gg1);
            atomicAdd(&g_denom[i2], gg2);
            g_idx[t] = i1 | (i2 << 8);
            g_val[t] = make_float2(gg1, gg2);
            if (v2 - v3 < THETA) {
                const int fi = atomicAdd(&g_nflag, 1);
                g_flag[fi] = t;
            }
        }
    }
}

// Exact fp32 recompute for margin-flagged tokens. The sequential-k fmaf order
// is load-bearing; only the LOAD SCHEDULE changed: 4-stage x 16-wide rotating
// register prefetch (fully unrolled -> wbuf stays in registers, MLP ~16-48).
__global__ void __launch_bounds__(64) fixup_k(
    const float* __restrict__ x,
    const float* __restrict__ b)
{
    __shared__ __align__(16) float xs[DIMK];
    __shared__ float lg[NEXP];
    const int nf = g_nflag;
    const int e = threadIdx.x;
    for (int i = blockIdx.x; i < nf; i += gridDim.x) {
        const int t = g_flag[i];
        const float4* xsrc = (const float4*)(x + (size_t)t * DIMK);
#pragma unroll
        for (int p = 0; p < 4; p++)
            ((float4*)xs)[e + 64 * p] = xsrc[e + 64 * p];
        __syncthreads();
        const float* wp = g_wT + e;
        float acc = 0.f;
        float wbuf[64];
#pragma unroll
        for (int j = 0; j < 48; j++) wbuf[j] = wp[(size_t)j * NEXP];
#pragma unroll
        for (int g = 0; g < 64; g++) {
            const int sl = (g & 3) * 16;
            const int pf = ((g + 3) & 3) * 16;
            if (g < 61) {
#pragma unroll
                for (int j = 0; j < 16; j++)
                    wbuf[pf + j] = wp[(size_t)(g * 16 + 48 + j) * NEXP];
            }
#pragma unroll
            for (int j = 0; j < 16; j++)
                acc = fmaf(xs[g * 16 + j], wbuf[sl + j], acc);
        }
        lg[e] = acc + b[e];
        __syncthreads();
        if (e == 0) {
            float v1 = lg[0], v2 = -3.4e38f;
            int n1 = 0, n2 = -1;
            for (int j = 1; j < NEXP; j++) {
                const float v = lg[j];
                if (v > v1)      { v2 = v1; n2 = n1; v1 = v; n1 = j; }
                else if (v > v2) { v2 = v; n2 = j; }
            }
            const int old = g_idx[t];
            const int o1 = old & 255, o2 = old >> 8;
            const bool same = (o1 == n1 && o2 == n2) || (o1 == n2 && o2 == n1);
            if (!same) {
                float s = 0.f;
                for (int j = 0; j < NEXP; j++) s += expf(lg[j] - v1);
                const float ng1 = 1.0f / s;
                const float ng2 = expf(v2 - v1) / s;
                const float2 ov = g_val[t];
                atomicAdd(&g_denom[o1], -ov.x);
                atomicAdd(&g_denom[o2], -ov.y);
                atomicAdd(&g_denom[n1], ng1);
                atomicAdd(&g_denom[n2], ng2);
                g_idx[t] = n1 | (n2 << 8);
                g_val[t] = make_float2(ng1, ng2);
            }
        }
        __syncthreads();
    }
}

// Single coalesced output pass: build each full row from (idx, val) sideband
// with the capacity/denom scaling applied. 16 threads/token, float4 stores.
__global__ void __launch_bounds__(256) scale_out_k(float* __restrict__ out) {
    __shared__ float sc[NEXP];
    const int tid = threadIdx.x;
    if (tid < NEXP) sc[tid] = 262144.0f / (g_denom[tid] + 1e-6f);
    __syncthreads();
    const int t   = blockIdx.x * 16 + (tid >> 4);
    const int sub = tid & 15;
    const int packed = g_idx[t];
    const float2 g = g_val[t];
    const int i1 = packed & 255;
    const int i2 = packed >> 8;
    const float s1 = g.x * sc[i1];
    const float s2 = g.y * sc[i2];
    const int e0 = sub * 4;
    float4 w;
    w.x = (i1 == e0)     ? s1 : (i2 == e0)     ? s2 : 0.0f;
    w.y = (i1 == e0 + 1) ? s1 : (i2 == e0 + 1) ? s2 : 0.0f;
    w.z = (i1 == e0 + 2) ? s1 : (i2 == e0 + 2) ? s2 : 0.0f;
    w.w = (i1 == e0 + 3) ? s1 : (i2 == e0 + 3) ? s2 : 0.0f;
    *(float4*)(out + (size_t)t * NEXP + e0) = w;
}

extern "C" void kernel_launch(void* const* d_in, const int* in_sizes, int n_in,
                              void* d_out, int out_size) {
    const float* x = (const float*)d_in[0];
    const float* W = (const float*)d_in[1];
    const float* b = (const float*)d_in[2];
    float* out = (float*)d_out;

    cudaFuncSetAttribute(gate_main_k, cudaFuncAttributeMaxDynamicSharedMemorySize, SMEM_DYN);

    zero_k<<<1, 64>>>();
    prep_w_k<<<NCH, 256>>>(W);
    gate_main_k<<<N_TOK / TM, 128, SMEM_DYN>>>(x, b);
    fixup_k<<<4096, 64>>>(x, b);
    scale_out_k<<<N_TOK / 16, 256>>>(out);
}